// round 5
// baseline (speedup 1.0000x reference)
#include <cuda_runtime.h>
#include <cuda_bf16.h>
#include <mma.h>

using namespace nvcuda;
typedef __nv_bfloat16 bf16;

#define CC   128
#define NB   9
#define RPD  8
#define HID  128
#define NTOK 32768
#define MROW 144   // 16 tokens * 9 edges

// ---- device scratch (no runtime allocation) ----
__device__ bf16  g_normbf[NTOK*CC];
__device__ float g_cd[NTOK*HID];
__device__ float g_cr[NTOK*HID];
__device__ bf16  g_Ad[CC*HID], g_Ar[CC*HID];   // Wn - Wd
__device__ bf16  g_Bd[CC*HID], g_Br[CC*HID];   // Wc + Wd
__device__ bf16  g_vWb[CC*CC], g_oWb[CC*CC];
__device__ float g_relbd[NB*HID], g_relbr[NB*HID];

__device__ __forceinline__ float gelu_exact(float x) {
    return 0.5f * x * (1.0f + erff(x * 0.70710678f));
}

// ================= kernel 0: fold weights, rel-bias tables =================
__global__ void k_prep(const float* __restrict__ dW1, const float* __restrict__ rW1,
                       const float* __restrict__ vW,  const float* __restrict__ oW,
                       const float* __restrict__ rel_pos,
                       const float* __restrict__ db1, const float* __restrict__ rb1)
{
    int i = blockIdx.x * blockDim.x + threadIdx.x;
    if (i >= CC*HID) return;
    int c = i >> 7, h = i & 127;
    g_Ad[i] = __float2bfloat16(dW1[(CC+c)*HID+h]   - dW1[(2*CC+c)*HID+h]);
    g_Bd[i] = __float2bfloat16(dW1[c*HID+h]        + dW1[(2*CC+c)*HID+h]);
    g_Ar[i] = __float2bfloat16(rW1[(CC+c)*HID+h]   - rW1[(2*CC+c)*HID+h]);
    g_Br[i] = __float2bfloat16(rW1[c*HID+h]        + rW1[(2*CC+c)*HID+h]);
    g_vWb[i] = __float2bfloat16(vW[i]);
    g_oWb[i] = __float2bfloat16(oW[i]);
    if (i < NB*HID) {
        int n = i >> 7;
        float sd = db1[h], sr = rb1[h];
        #pragma unroll
        for (int r = 0; r < RPD; r++) {
            float rp = rel_pos[n*RPD + r];
            sd += rp * dW1[(3*CC+r)*HID+h];
            sr += rp * rW1[(3*CC+r)*HID+h];
        }
        g_relbd[i] = sd; g_relbr[i] = sr;
    }
}

// ================= kernel 1: LayerNorm1 -> bf16 =================
__global__ void k_ln1(const float* __restrict__ tokens,
                      const float* __restrict__ g, const float* __restrict__ b)
{
    int wid = threadIdx.x >> 5, lane = threadIdx.x & 31;
    int row = blockIdx.x * 8 + wid;
    float4 v = reinterpret_cast<const float4*>(tokens + (size_t)row*CC)[lane];
    float s = v.x + v.y + v.z + v.w;
    #pragma unroll
    for (int o = 16; o; o >>= 1) s += __shfl_xor_sync(0xffffffffu, s, o);
    float mean = s * (1.0f/128.0f);
    float d0=v.x-mean, d1=v.y-mean, d2=v.z-mean, d3=v.w-mean;
    float q = d0*d0+d1*d1+d2*d2+d3*d3;
    #pragma unroll
    for (int o = 16; o; o >>= 1) q += __shfl_xor_sync(0xffffffffu, q, o);
    float rstd = rsqrtf(q * (1.0f/128.0f) + 1e-5f);
    float4 gg = reinterpret_cast<const float4*>(g)[lane];
    float4 bb = reinterpret_cast<const float4*>(b)[lane];
    __nv_bfloat162 p0 = __floats2bfloat162_rn(d0*rstd*gg.x+bb.x, d1*rstd*gg.y+bb.y);
    __nv_bfloat162 p1 = __floats2bfloat162_rn(d2*rstd*gg.z+bb.z, d3*rstd*gg.w+bb.w);
    uint2 pk; pk.x = *reinterpret_cast<unsigned int*>(&p0); pk.y = *reinterpret_cast<unsigned int*>(&p1);
    reinterpret_cast<uint2*>(g_normbf + (size_t)row*CC)[lane] = pk;
}

// ================= kernel 2: center GEMMs (N @ Bd, N @ Br) =================
#define CSMEM (3*128*136*2)
__global__ void __launch_bounds__(256) k_center()
{
    extern __shared__ char sm[];
    bf16* Xs = reinterpret_cast<bf16*>(sm);
    bf16* Wd = Xs + 128*136;
    bf16* Wr = Wd + 128*136;
    int tid = threadIdx.x, wid = tid >> 5;
    int row0 = blockIdx.x * 128;
    for (int i = tid; i < 8192; i += 256) {
        int r = i >> 6, c = i & 63;
        reinterpret_cast<unsigned int*>(Wd)[r*68+c] = reinterpret_cast<const unsigned int*>(g_Bd)[i];
        reinterpret_cast<unsigned int*>(Wr)[r*68+c] = reinterpret_cast<const unsigned int*>(g_Br)[i];
        reinterpret_cast<unsigned int*>(Xs)[r*68+c] =
            reinterpret_cast<const unsigned int*>(g_normbf + (size_t)row0*CC)[i];
    }
    __syncthreads();
    wmma::fragment<wmma::matrix_a,16,16,16,bf16,wmma::row_major> fa;
    wmma::fragment<wmma::matrix_b,16,16,16,bf16,wmma::row_major> fb;
    wmma::fragment<wmma::accumulator,16,16,16,float> acc[8];
    #pragma unroll
    for (int ct = 0; ct < 8; ct++) wmma::fill_fragment(acc[ct], 0.0f);
    for (int kt = 0; kt < 8; kt++) {
        wmma::load_matrix_sync(fa, Xs + wid*16*136 + kt*16, 136);
        #pragma unroll
        for (int ct = 0; ct < 8; ct++) {
            wmma::load_matrix_sync(fb, Wd + kt*16*136 + ct*16, 136);
            wmma::mma_sync(acc[ct], fa, fb, acc[ct]);
        }
    }
    #pragma unroll
    for (int ct = 0; ct < 8; ct++)
        wmma::store_matrix_sync(g_cd + (size_t)(row0+wid*16)*HID + ct*16, acc[ct], HID, wmma::mem_row_major);
    #pragma unroll
    for (int ct = 0; ct < 8; ct++) wmma::fill_fragment(acc[ct], 0.0f);
    for (int kt = 0; kt < 8; kt++) {
        wmma::load_matrix_sync(fa, Xs + wid*16*136 + kt*16, 136);
        #pragma unroll
        for (int ct = 0; ct < 8; ct++) {
            wmma::load_matrix_sync(fb, Wr + kt*16*136 + ct*16, 136);
            wmma::mma_sync(acc[ct], fa, fb, acc[ct]);
        }
    }
    #pragma unroll
    for (int ct = 0; ct < 8; ct++)
        wmma::store_matrix_sync(g_cr + (size_t)(row0+wid*16)*HID + ct*16, acc[ct], HID, wmma::mem_row_major);
}

// ================= main fused kernel =================
struct SmemMain {
    bf16 W0[128*136];
    bf16 W1[128*136];
    bf16 Vs[MROW*136];
    union {
        float Hs[MROW*132];
        struct {
            bf16  mv [16*136];
            float Ms [16*128];
            bf16  msg[16*136];
            float Us [16*128];
        } e;
    } u;
    float Cds[16*128], Crs[16*128];
    float relbd[NB*128], relbr[NB*128];
    float w2d[128], w2r[128];
    float drive[MROW], resist[MROW], gate[MROW];
    float gsum[16], invm[16];
};

__global__ void __launch_bounds__(288, 1) k_main(
    const float* __restrict__ tokens,
    const float* __restrict__ ln2g, const float* __restrict__ ln2b,
    const float* __restrict__ dW2,  const float* __restrict__ db2,
    const float* __restrict__ rW2,  const float* __restrict__ rb2,
    const float* __restrict__ vb,   const float* __restrict__ ob,
    const float* __restrict__ pg, const float* __restrict__ pl, const float* __restrict__ pb,
    float* __restrict__ out)
{
    extern __shared__ char smraw[];
    SmemMain& S = *reinterpret_cast<SmemMain*>(smraw);
    const int tid = threadIdx.x, wid = tid >> 5, lane = tid & 31;
    const int bx = blockIdx.x;
    const int x0 = (bx & 7) << 4, y = (bx >> 3) & 127, b = bx >> 10;
    const int tokrow0 = (b*128 + y)*128 + x0;

    // ---- stage weights / biases / center terms ----
    for (int i = tid; i < 8192; i += 288) {
        int r = i >> 6, c = i & 63;
        reinterpret_cast<unsigned int*>(S.W0)[r*68+c] = reinterpret_cast<const unsigned int*>(g_Ad)[i];
        reinterpret_cast<unsigned int*>(S.W1)[r*68+c] = reinterpret_cast<const unsigned int*>(g_Ar)[i];
    }
    for (int i = tid; i < NB*HID; i += 288) { S.relbd[i] = g_relbd[i]; S.relbr[i] = g_relbr[i]; }
    for (int i = tid; i < 2048; i += 288) {
        S.Cds[i] = g_cd[(size_t)tokrow0*HID + i];
        S.Crs[i] = g_cr[(size_t)tokrow0*HID + i];
    }
    if (tid < 128) { S.w2d[tid] = dW2[tid]; S.w2r[tid] = rW2[tid]; }

    // ---- gather scrambled neighborhood: Vs[t*9+n][c2] = norm[y+si-1, x+sj-1, c],
    //      where c*9+s = n*128+c2  (torch reshape semantics) ----
    for (int uidx = tid; uidx < 2304; uidx += 288) {
        int t = uidx / 144, rem = uidx - t*144;
        int s = rem >> 4, c0 = (rem & 15) << 3;
        int si = s / 3, sj = s - si*3;
        int yy = y + si - 1, xx = x0 + t + sj - 1;
        union { uint4 v; unsigned short h[8]; } pkt;
        if (yy >= 0 && yy < 128 && xx >= 0 && xx < 128) {
            const uint4* src = reinterpret_cast<const uint4*>(
                g_normbf + ((size_t)((b*128+yy)*128+xx))*CC + c0);
            pkt.v = *src;
        } else {
            pkt.v = make_uint4(0,0,0,0);
        }
        unsigned short* vsrow = reinterpret_cast<unsigned short*>(S.Vs);
        #pragma unroll
        for (int k = 0; k < 8; k++) {
            int p = (c0 + k)*9 + s;
            vsrow[(t*9 + (p >> 7))*136 + (p & 127)] = pkt.h[k];
        }
    }
    __syncthreads();

    // ---- per-warp band GEMM + epilogue (drive then resistance) ----
    {
        wmma::fragment<wmma::matrix_a,16,16,16,bf16,wmma::row_major> fa;
        wmma::fragment<wmma::matrix_b,16,16,16,bf16,wmma::row_major> fb;
        wmma::fragment<wmma::accumulator,16,16,16,float> acc[8];
        const float db2v = db2[0], rb2v = rb2[0];
        for (int pass = 0; pass < 2; pass++) {
            const bf16* Wsm = pass ? S.W1 : S.W0;
            #pragma unroll
            for (int ct = 0; ct < 8; ct++) wmma::fill_fragment(acc[ct], 0.0f);
            for (int kt = 0; kt < 8; kt++) {
                wmma::load_matrix_sync(fa, S.Vs + wid*16*136 + kt*16, 136);
                #pragma unroll
                for (int ct = 0; ct < 8; ct++) {
                    wmma::load_matrix_sync(fb, Wsm + kt*16*136 + ct*16, 136);
                    wmma::mma_sync(acc[ct], fa, fb, acc[ct]);
                }
            }
            #pragma unroll
            for (int ct = 0; ct < 8; ct++)
                wmma::store_matrix_sync(S.u.Hs + wid*16*132 + ct*16, acc[ct], 132, wmma::mem_row_major);
            __syncwarp();
            const float* Cs  = pass ? S.Crs : S.Cds;
            const float* rlb = pass ? S.relbr : S.relbd;
            const float* w2  = pass ? S.w2r : S.w2d;
            float* dst = pass ? S.resist : S.drive;
            float bsc = pass ? rb2v : db2v;
            float4 wv = reinterpret_cast<const float4*>(w2)[lane];
            for (int rr = 0; rr < 16; rr++) {
                int r = wid*16 + rr;
                int t = r / 9, n = r - t*9;
                float4 hv = reinterpret_cast<const float4*>(S.u.Hs + r*132)[lane];
                float4 cv = reinterpret_cast<const float4*>(Cs + t*128)[lane];
                float4 bv = reinterpret_cast<const float4*>(rlb + n*128)[lane];
                float sacc = gelu_exact(hv.x+cv.x+bv.x)*wv.x
                           + gelu_exact(hv.y+cv.y+bv.y)*wv.y
                           + gelu_exact(hv.z+cv.z+bv.z)*wv.z
                           + gelu_exact(hv.w+cv.w+bv.w)*wv.w;
                #pragma unroll
                for (int o = 16; o; o >>= 1) sacc += __shfl_xor_sync(0xffffffffu, sacc, o);
                if (lane == 0) dst[r] = sacc + bsc;
            }
            __syncwarp();
        }
    }
    __syncthreads();

    // ---- gate ----
    if (tid < MROW) {
        float gamma = pg[0], lam = pl[0], bias = pb[0];
        float rres = S.resist[tid];
        float sp = (rres > 20.f) ? rres : log1pf(expf(rres));
        float e = gamma * S.drive[tid] / (lam * sp + 1e-6f) + bias;
        e = fminf(fmaxf(e, -3.0f), 3.0f);
        S.gate[tid] = 1.0f / (1.0f + expf(-e));
    }
    __syncthreads();
    if (tid < 16) {
        float sgm = 0.f;
        #pragma unroll
        for (int n = 0; n < 9; n++) sgm += S.gate[tid*9+n];
        S.gsum[tid] = sgm;
        S.invm[tid] = 1.0f / fmaxf(sgm, 1e-6f);
    }
    // ---- gated neighbor sum -> mv (bf16 16x128) ----
    for (int uidx = tid; uidx < 2048; uidx += 288) {
        int t = uidx >> 7, c = uidx & 127;
        float sacc = 0.f;
        #pragma unroll
        for (int n = 0; n < 9; n++)
            sacc += S.gate[t*9+n] * __bfloat162float(S.Vs[(t*9+n)*136 + c]);
        S.u.e.mv[t*136 + c] = __float2bfloat16(sacc);
    }
    __syncthreads();

    // ---- mv @ vW (wmma, fb from global) ----
    if (wid < 8) {
        wmma::fragment<wmma::matrix_a,16,16,16,bf16,wmma::row_major> fa;
        wmma::fragment<wmma::matrix_b,16,16,16,bf16,wmma::row_major> fb;
        wmma::fragment<wmma::accumulator,16,16,16,float> acc;
        wmma::fill_fragment(acc, 0.0f);
        for (int kt = 0; kt < 8; kt++) {
            wmma::load_matrix_sync(fa, S.u.e.mv + kt*16, 136);
            wmma::load_matrix_sync(fb, g_vWb + kt*16*128 + wid*16, 128);
            wmma::mma_sync(acc, fa, fb, acc);
        }
        wmma::store_matrix_sync(S.u.e.Ms + wid*16, acc, 128, wmma::mem_row_major);
    }
    __syncthreads();
    // ---- message = (mv@vW + gsum*vb) / mass, to bf16 ----
    for (int uidx = tid; uidx < 2048; uidx += 288) {
        int t = uidx >> 7, d = uidx & 127;
        float m = (S.u.e.Ms[t*128+d] + S.gsum[t]*vb[d]) * S.invm[t];
        S.u.e.msg[t*136 + d] = __float2bfloat16(m);
    }
    __syncthreads();
    // ---- message @ oW ----
    if (wid < 8) {
        wmma::fragment<wmma::matrix_a,16,16,16,bf16,wmma::row_major> fa;
        wmma::fragment<wmma::matrix_b,16,16,16,bf16,wmma::row_major> fb;
        wmma::fragment<wmma::accumulator,16,16,16,float> acc;
        wmma::fill_fragment(acc, 0.0f);
        for (int kt = 0; kt < 8; kt++) {
            wmma::load_matrix_sync(fa, S.u.e.msg + kt*16, 136);
            wmma::load_matrix_sync(fb, g_oWb + kt*16*128 + wid*16, 128);
            wmma::mma_sync(acc, fa, fb, acc);
        }
        wmma::store_matrix_sync(S.u.e.Us + wid*16, acc, 128, wmma::mem_row_major);
    }
    __syncthreads();
    // ---- LN2(tokens + update) ----
    for (int r = wid; r < 16; r += 9) {
        size_t grow = (size_t)(tokrow0 + r) * CC;
        float4 tv = reinterpret_cast<const float4*>(tokens + grow)[lane];
        float4 uv = reinterpret_cast<const float4*>(S.u.e.Us + r*128)[lane];
        float4 ov = reinterpret_cast<const float4*>(ob)[lane];
        float v0 = tv.x+uv.x+ov.x, v1 = tv.y+uv.y+ov.y;
        float v2 = tv.z+uv.z+ov.z, v3 = tv.w+uv.w+ov.w;
        float s = v0+v1+v2+v3;
        #pragma unroll
        for (int o = 16; o; o >>= 1) s += __shfl_xor_sync(0xffffffffu, s, o);
        float mean = s * (1.0f/128.0f);
        float d0=v0-mean, d1=v1-mean, d2=v2-mean, d3=v3-mean;
        float q = d0*d0+d1*d1+d2*d2+d3*d3;
        #pragma unroll
        for (int o = 16; o; o >>= 1) q += __shfl_xor_sync(0xffffffffu, q, o);
        float rstd = rsqrtf(q * (1.0f/128.0f) + 1e-5f);
        float4 gg = reinterpret_cast<const float4*>(ln2g)[lane];
        float4 bb = reinterpret_cast<const float4*>(ln2b)[lane];
        float4 o4;
        o4.x = d0*rstd*gg.x+bb.x; o4.y = d1*rstd*gg.y+bb.y;
        o4.z = d2*rstd*gg.z+bb.z; o4.w = d3*rstd*gg.w+bb.w;
        reinterpret_cast<float4*>(out + grow)[lane] = o4;
    }
}

// ================= launch =================
extern "C" void kernel_launch(void* const* d_in, const int* in_sizes, int n_in,
                              void* d_out, int out_size)
{
    const float* tokens = (const float*)d_in[0];
    const float* ln1g   = (const float*)d_in[1];
    const float* ln1b   = (const float*)d_in[2];
    const float* ln2g   = (const float*)d_in[3];
    const float* ln2b   = (const float*)d_in[4];
    const float* relp   = (const float*)d_in[5];
    const float* dW1    = (const float*)d_in[6];
    const float* db1    = (const float*)d_in[7];
    const float* dW2    = (const float*)d_in[8];
    const float* db2    = (const float*)d_in[9];
    const float* rW1    = (const float*)d_in[10];
    const float* rb1    = (const float*)d_in[11];
    const float* rW2    = (const float*)d_in[12];
    const float* rb2    = (const float*)d_in[13];
    const float* vW     = (const float*)d_in[14];
    const float* vb     = (const float*)d_in[15];
    const float* oW     = (const float*)d_in[16];
    const float* ob     = (const float*)d_in[17];
    const float* pg     = (const float*)d_in[18];
    const float* pl     = (const float*)d_in[19];
    const float* pb     = (const float*)d_in[20];
    float* out = (float*)d_out;

    static_assert(sizeof(SmemMain) <= 232448, "smem too big");
    cudaFuncSetAttribute(k_center, cudaFuncAttributeMaxDynamicSharedMemorySize, CSMEM);
    cudaFuncSetAttribute(k_main, cudaFuncAttributeMaxDynamicSharedMemorySize, (int)sizeof(SmemMain));

    k_prep<<<64, 256>>>(dW1, rW1, vW, oW, relp, db1, rb1);
    k_ln1<<<4096, 256>>>(tokens, ln1g, ln1b);
    k_center<<<256, 256, CSMEM>>>();
    k_main<<<2048, 288, sizeof(SmemMain)>>>(tokens, ln2g, ln2b, dW2, db2, rW2, rb2,
                                            vb, ob, pg, pl, pb, out);
}

// round 6
// speedup vs baseline: 1.2293x; 1.2293x over previous
#include <cuda_runtime.h>
#include <cuda_bf16.h>
#include <mma.h>

using namespace nvcuda;
typedef __nv_bfloat16 bf16;

#define CC   128
#define NB   9
#define RPD  8
#define HID  128
#define NTOK 32768
#define MROW 144   // 16 tokens * 9 edges

// ---- device scratch (no runtime allocation) ----
__device__ bf16  g_normbf[NTOK*CC];
__device__ float g_cd[NTOK*HID];
__device__ float g_cr[NTOK*HID];
__device__ bf16  g_Ad[CC*HID], g_Ar[CC*HID];   // Wn - Wd
__device__ bf16  g_Bd[CC*HID], g_Br[CC*HID];   // Wc + Wd
__device__ bf16  g_vWb[CC*CC], g_oWb[CC*CC];
__device__ float g_relbd[NB*HID], g_relbr[NB*HID];

__device__ __forceinline__ float gelu_exact(float x) {
    return 0.5f * x * (1.0f + erff(x * 0.70710678f));
}

// ================= kernel 0: fold weights, rel-bias tables =================
__global__ void k_prep(const float* __restrict__ dW1, const float* __restrict__ rW1,
                       const float* __restrict__ vW,  const float* __restrict__ oW,
                       const float* __restrict__ rel_pos,
                       const float* __restrict__ db1, const float* __restrict__ rb1)
{
    int i = blockIdx.x * blockDim.x + threadIdx.x;
    if (i >= CC*HID) return;
    int c = i >> 7, h = i & 127;
    g_Ad[i] = __float2bfloat16(dW1[(CC+c)*HID+h]   - dW1[(2*CC+c)*HID+h]);
    g_Bd[i] = __float2bfloat16(dW1[c*HID+h]        + dW1[(2*CC+c)*HID+h]);
    g_Ar[i] = __float2bfloat16(rW1[(CC+c)*HID+h]   - rW1[(2*CC+c)*HID+h]);
    g_Br[i] = __float2bfloat16(rW1[c*HID+h]        + rW1[(2*CC+c)*HID+h]);
    g_vWb[i] = __float2bfloat16(vW[i]);
    g_oWb[i] = __float2bfloat16(oW[i]);
    if (i < NB*HID) {
        int n = i >> 7;
        float sd = db1[h], sr = rb1[h];
        #pragma unroll
        for (int r = 0; r < RPD; r++) {
            float rp = rel_pos[n*RPD + r];
            sd += rp * dW1[(3*CC+r)*HID+h];
            sr += rp * rW1[(3*CC+r)*HID+h];
        }
        g_relbd[i] = sd; g_relbr[i] = sr;
    }
}

// ================= kernel 1: LayerNorm1 -> bf16 =================
__global__ void k_ln1(const float* __restrict__ tokens,
                      const float* __restrict__ g, const float* __restrict__ b)
{
    int wid = threadIdx.x >> 5, lane = threadIdx.x & 31;
    int row = blockIdx.x * 8 + wid;
    float4 v = reinterpret_cast<const float4*>(tokens + (size_t)row*CC)[lane];
    float s = v.x + v.y + v.z + v.w;
    #pragma unroll
    for (int o = 16; o; o >>= 1) s += __shfl_xor_sync(0xffffffffu, s, o);
    float mean = s * (1.0f/128.0f);
    float d0=v.x-mean, d1=v.y-mean, d2=v.z-mean, d3=v.w-mean;
    float q = d0*d0+d1*d1+d2*d2+d3*d3;
    #pragma unroll
    for (int o = 16; o; o >>= 1) q += __shfl_xor_sync(0xffffffffu, q, o);
    float rstd = rsqrtf(q * (1.0f/128.0f) + 1e-5f);
    float4 gg = reinterpret_cast<const float4*>(g)[lane];
    float4 bb = reinterpret_cast<const float4*>(b)[lane];
    __nv_bfloat162 p0 = __floats2bfloat162_rn(d0*rstd*gg.x+bb.x, d1*rstd*gg.y+bb.y);
    __nv_bfloat162 p1 = __floats2bfloat162_rn(d2*rstd*gg.z+bb.z, d3*rstd*gg.w+bb.w);
    uint2 pk; pk.x = *reinterpret_cast<unsigned int*>(&p0); pk.y = *reinterpret_cast<unsigned int*>(&p1);
    reinterpret_cast<uint2*>(g_normbf + (size_t)row*CC)[lane] = pk;
}

// ================= kernel 2: center GEMMs (split drive/resist by blockIdx.y) =========
#define CSMEM (2*128*136*2)
__global__ void __launch_bounds__(256) k_center()
{
    extern __shared__ char sm[];
    bf16* Xs = reinterpret_cast<bf16*>(sm);
    bf16* Ws = Xs + 128*136;
    int tid = threadIdx.x, wid = tid >> 5;
    int row0 = blockIdx.x * 128;
    int which = blockIdx.y;          // 0 = drive (Bd->g_cd), 1 = resist (Br->g_cr)
    const bf16* Wg = which ? g_Br : g_Bd;
    float* outg = which ? g_cr : g_cd;
    for (int i = tid; i < 8192; i += 256) {
        int r = i >> 6, c = i & 63;
        reinterpret_cast<unsigned int*>(Ws)[r*68+c] = reinterpret_cast<const unsigned int*>(Wg)[i];
        reinterpret_cast<unsigned int*>(Xs)[r*68+c] =
            reinterpret_cast<const unsigned int*>(g_normbf + (size_t)row0*CC)[i];
    }
    __syncthreads();
    wmma::fragment<wmma::matrix_a,16,16,16,bf16,wmma::row_major> fa;
    wmma::fragment<wmma::matrix_b,16,16,16,bf16,wmma::row_major> fb;
    wmma::fragment<wmma::accumulator,16,16,16,float> acc[8];
    #pragma unroll
    for (int ct = 0; ct < 8; ct++) wmma::fill_fragment(acc[ct], 0.0f);
    for (int kt = 0; kt < 8; kt++) {
        wmma::load_matrix_sync(fa, Xs + wid*16*136 + kt*16, 136);
        #pragma unroll
        for (int ct = 0; ct < 8; ct++) {
            wmma::load_matrix_sync(fb, Ws + kt*16*136 + ct*16, 136);
            wmma::mma_sync(acc[ct], fa, fb, acc[ct]);
        }
    }
    #pragma unroll
    for (int ct = 0; ct < 8; ct++)
        wmma::store_matrix_sync(outg + (size_t)(row0+wid*16)*HID + ct*16, acc[ct], HID, wmma::mem_row_major);
}

// ================= main fused kernel =================
#define WS 272   // Wcat bf16 stride (cols 0-127 drive, 128-255 resist)
struct SmemMain {
    bf16 Wcat[128*WS];            // 69.6 KB
    bf16 Vs[MROW*136];            // 39.2 KB
    union {
        float tile[18*16*20];     // per-warp epilogue tiles, 23 KB
        struct {
            bf16  mv [16*136];
            float Ms [16*128];
            bf16  msg[16*136];
            float Us [16*128];
        } e;
    } u;
    float Cds[16*128], Crs[16*128];
    float relbd[NB*128], relbr[NB*128];
    float w2d[128], w2r[128];
    float drive[MROW], resist[MROW], gate[MROW];
    float gsum[16], invm[16];
};

__global__ void __launch_bounds__(576, 1) k_main(
    const float* __restrict__ tokens,
    const float* __restrict__ ln2g, const float* __restrict__ ln2b,
    const float* __restrict__ dW2,  const float* __restrict__ db2,
    const float* __restrict__ rW2,  const float* __restrict__ rb2,
    const float* __restrict__ vb,   const float* __restrict__ ob,
    const float* __restrict__ pg, const float* __restrict__ pl, const float* __restrict__ pb,
    float* __restrict__ out)
{
    extern __shared__ char smraw[];
    SmemMain& S = *reinterpret_cast<SmemMain*>(smraw);
    const int tid = threadIdx.x, wid = tid >> 5, lane = tid & 31;
    const int bx = blockIdx.x;
    const int x0 = (bx & 7) << 4, y = (bx >> 3) & 127, b = bx >> 10;
    const int tokrow0 = (b*128 + y)*128 + x0;

    // ---- stage concatenated weight [Ad | Ar], biases, center terms ----
    for (int i = tid; i < 8192; i += 576) {
        int r = i >> 6, c = i & 63;
        unsigned int* Wu = reinterpret_cast<unsigned int*>(S.Wcat);
        Wu[r*(WS/2) + c]      = reinterpret_cast<const unsigned int*>(g_Ad)[i];
        Wu[r*(WS/2) + 64 + c] = reinterpret_cast<const unsigned int*>(g_Ar)[i];
    }
    for (int i = tid; i < NB*HID; i += 576) { S.relbd[i] = g_relbd[i]; S.relbr[i] = g_relbr[i]; }
    for (int i = tid; i < 2048; i += 576) {
        S.Cds[i] = g_cd[(size_t)tokrow0*HID + i];
        S.Crs[i] = g_cr[(size_t)tokrow0*HID + i];
    }
    if (tid < 128) S.w2d[tid] = dW2[tid];
    else if (tid < 256) S.w2r[tid-128] = rW2[tid-128];

    // ---- gather scrambled neighborhood: Vs[t*9+n][c2] = norm[y+si-1, x+sj-1, c],
    //      where c*9+s = n*128+c2 (torch reshape semantics) ----
    for (int uidx = tid; uidx < 2304; uidx += 576) {
        int t = uidx / 144, rem = uidx - t*144;
        int s = rem >> 4, c0 = (rem & 15) << 3;
        int si = s / 3, sj = s - si*3;
        int yy = y + si - 1, xx = x0 + t + sj - 1;
        union { uint4 v; unsigned short h[8]; } pkt;
        if (yy >= 0 && yy < 128 && xx >= 0 && xx < 128) {
            pkt.v = *reinterpret_cast<const uint4*>(
                g_normbf + ((size_t)((b*128+yy)*128+xx))*CC + c0);
        } else {
            pkt.v = make_uint4(0,0,0,0);
        }
        unsigned short* vsrow = reinterpret_cast<unsigned short*>(S.Vs);
        #pragma unroll
        for (int k = 0; k < 8; k++) {
            int p = (c0 + k)*9 + s;
            vsrow[(t*9 + (p >> 7))*136 + (p & 127)] = pkt.h[k];
        }
    }
    __syncthreads();

    // ---- one wide GEMM phase: 18 warps = 9 bands x {drive,resist},
    //      epilogue (addend + GELU + w2-dot) fused per 16x16 tile ----
    {
        const int band = wid >> 1, half = wid & 1;
        const bf16* Wbase = S.Wcat + half*128;          // column offset into Wcat
        float* tb = S.u.tile + wid*(16*20);
        const float* Cs  = half ? S.Crs  : S.Cds;
        const float* rlb = half ? S.relbr : S.relbd;
        const float* w2  = half ? S.w2r  : S.w2d;
        const float b2v  = half ? rb2[0] : db2[0];
        float* dst = half ? S.resist : S.drive;

        wmma::fragment<wmma::matrix_a,16,16,16,bf16,wmma::row_major> fa[8];
        #pragma unroll
        for (int kt = 0; kt < 8; kt++)
            wmma::load_matrix_sync(fa[kt], S.Vs + band*16*136 + kt*16, 136);

        const int rloc = lane >> 1;                 // 0..15 row within band
        const int r0 = band*16 + rloc;              // 0..143
        const int t = r0 / 9, n = r0 - t*9;
        const int coff = (lane & 1) * 8;            // col half within tile
        float preg = 0.0f;

        wmma::fragment<wmma::matrix_b,16,16,16,bf16,wmma::row_major> fb;
        wmma::fragment<wmma::accumulator,16,16,16,float> acc;
        for (int ct = 0; ct < 8; ct++) {
            wmma::fill_fragment(acc, 0.0f);
            #pragma unroll
            for (int kt = 0; kt < 8; kt++) {
                wmma::load_matrix_sync(fb, Wbase + kt*16*WS + ct*16, WS);
                wmma::mma_sync(acc, fa[kt], fb, acc);
            }
            wmma::store_matrix_sync(tb, acc, 20, wmma::mem_row_major);
            __syncwarp();
            const int cbase = ct*16 + coff;
            const float* trow = tb + rloc*20 + coff;
            #pragma unroll
            for (int k = 0; k < 8; k++) {
                float h = trow[k] + Cs[t*128 + cbase + k] + rlb[n*128 + cbase + k];
                preg += gelu_exact(h) * w2[cbase + k];
            }
            __syncwarp();
        }
        preg += __shfl_xor_sync(0xffffffffu, preg, 1);
        if ((lane & 1) == 0) dst[r0] = preg + b2v;
    }
    __syncthreads();

    // ---- gate ----
    if (tid < MROW) {
        float gamma = pg[0], lam = pl[0], bias = pb[0];
        float rres = S.resist[tid];
        float sp = (rres > 20.f) ? rres : log1pf(expf(rres));
        float e = gamma * S.drive[tid] / (lam * sp + 1e-6f) + bias;
        e = fminf(fmaxf(e, -3.0f), 3.0f);
        S.gate[tid] = 1.0f / (1.0f + expf(-e));
    }
    __syncthreads();
    if (tid < 16) {
        float sgm = 0.f;
        #pragma unroll
        for (int n2 = 0; n2 < 9; n2++) sgm += S.gate[tid*9+n2];
        S.gsum[tid] = sgm;
        S.invm[tid] = 1.0f / fmaxf(sgm, 1e-6f);
    }
    // ---- gated neighbor sum -> mv (bf16 16x128) ----
    for (int uidx = tid; uidx < 2048; uidx += 576) {
        int t2 = uidx >> 7, c = uidx & 127;
        float sacc = 0.f;
        #pragma unroll
        for (int n2 = 0; n2 < 9; n2++)
            sacc += S.gate[t2*9+n2] * __bfloat162float(S.Vs[(t2*9+n2)*136 + c]);
        S.u.e.mv[t2*136 + c] = __float2bfloat16(sacc);
    }
    __syncthreads();

    // ---- mv @ vW ----
    if (wid < 8) {
        wmma::fragment<wmma::matrix_a,16,16,16,bf16,wmma::row_major> fa;
        wmma::fragment<wmma::matrix_b,16,16,16,bf16,wmma::row_major> fb;
        wmma::fragment<wmma::accumulator,16,16,16,float> acc;
        wmma::fill_fragment(acc, 0.0f);
        for (int kt = 0; kt < 8; kt++) {
            wmma::load_matrix_sync(fa, S.u.e.mv + kt*16, 136);
            wmma::load_matrix_sync(fb, g_vWb + kt*16*128 + wid*16, 128);
            wmma::mma_sync(acc, fa, fb, acc);
        }
        wmma::store_matrix_sync(S.u.e.Ms + wid*16, acc, 128, wmma::mem_row_major);
    }
    __syncthreads();
    // ---- message = (mv@vW + gsum*vb) / mass, to bf16 ----
    for (int uidx = tid; uidx < 2048; uidx += 576) {
        int t2 = uidx >> 7, d = uidx & 127;
        float m = (S.u.e.Ms[t2*128+d] + S.gsum[t2]*vb[d]) * S.invm[t2];
        S.u.e.msg[t2*136 + d] = __float2bfloat16(m);
    }
    __syncthreads();
    // ---- message @ oW ----
    if (wid < 8) {
        wmma::fragment<wmma::matrix_a,16,16,16,bf16,wmma::row_major> fa;
        wmma::fragment<wmma::matrix_b,16,16,16,bf16,wmma::row_major> fb;
        wmma::fragment<wmma::accumulator,16,16,16,float> acc;
        wmma::fill_fragment(acc, 0.0f);
        for (int kt = 0; kt < 8; kt++) {
            wmma::load_matrix_sync(fa, S.u.e.msg + kt*16, 136);
            wmma::load_matrix_sync(fb, g_oWb + kt*16*128 + wid*16, 128);
            wmma::mma_sync(acc, fa, fb, acc);
        }
        wmma::store_matrix_sync(S.u.e.Us + wid*16, acc, 128, wmma::mem_row_major);
    }
    __syncthreads();
    // ---- LN2(tokens + update) ----
    for (int r = wid; r < 16; r += 18) {
        size_t grow = (size_t)(tokrow0 + r) * CC;
        float4 tv = reinterpret_cast<const float4*>(tokens + grow)[lane];
        float4 uv = reinterpret_cast<const float4*>(S.u.e.Us + r*128)[lane];
        float4 ov = reinterpret_cast<const float4*>(ob)[lane];
        float v0 = tv.x+uv.x+ov.x, v1 = tv.y+uv.y+ov.y;
        float v2 = tv.z+uv.z+ov.z, v3 = tv.w+uv.w+ov.w;
        float s = v0+v1+v2+v3;
        #pragma unroll
        for (int o = 16; o; o >>= 1) s += __shfl_xor_sync(0xffffffffu, s, o);
        float mean = s * (1.0f/128.0f);
        float d0=v0-mean, d1=v1-mean, d2=v2-mean, d3=v3-mean;
        float q = d0*d0+d1*d1+d2*d2+d3*d3;
        #pragma unroll
        for (int o = 16; o; o >>= 1) q += __shfl_xor_sync(0xffffffffu, q, o);
        float rstd = rsqrtf(q * (1.0f/128.0f) + 1e-5f);
        float4 gg = reinterpret_cast<const float4*>(ln2g)[lane];
        float4 bb = reinterpret_cast<const float4*>(ln2b)[lane];
        float4 o4;
        o4.x = d0*rstd*gg.x+bb.x; o4.y = d1*rstd*gg.y+bb.y;
        o4.z = d2*rstd*gg.z+bb.z; o4.w = d3*rstd*gg.w+bb.w;
        reinterpret_cast<float4*>(out + grow)[lane] = o4;
    }
}

// ================= launch =================
extern "C" void kernel_launch(void* const* d_in, const int* in_sizes, int n_in,
                              void* d_out, int out_size)
{
    const float* tokens = (const float*)d_in[0];
    const float* ln1g   = (const float*)d_in[1];
    const float* ln1b   = (const float*)d_in[2];
    const float* ln2g   = (const float*)d_in[3];
    const float* ln2b   = (const float*)d_in[4];
    const float* relp   = (const float*)d_in[5];
    const float* dW1    = (const float*)d_in[6];
    const float* db1    = (const float*)d_in[7];
    const float* dW2    = (const float*)d_in[8];
    const float* db2    = (const float*)d_in[9];
    const float* rW1    = (const float*)d_in[10];
    const float* rb1    = (const float*)d_in[11];
    const float* rW2    = (const float*)d_in[12];
    const float* rb2    = (const float*)d_in[13];
    const float* vW     = (const float*)d_in[14];
    const float* vb     = (const float*)d_in[15];
    const float* oW     = (const float*)d_in[16];
    const float* ob     = (const float*)d_in[17];
    const float* pg     = (const float*)d_in[18];
    const float* pl     = (const float*)d_in[19];
    const float* pb     = (const float*)d_in[20];
    float* out = (float*)d_out;

    static_assert(sizeof(SmemMain) <= 227000, "smem too big");
    cudaFuncSetAttribute(k_center, cudaFuncAttributeMaxDynamicSharedMemorySize, CSMEM);
    cudaFuncSetAttribute(k_main, cudaFuncAttributeMaxDynamicSharedMemorySize, (int)sizeof(SmemMain));

    k_prep<<<64, 256>>>(dW1, rW1, vW, oW, relp, db1, rb1);
    k_ln1<<<4096, 256>>>(tokens, ln1g, ln1b);
    dim3 cgrid(256, 2);
    k_center<<<cgrid, 256, CSMEM>>>();
    k_main<<<2048, 576, sizeof(SmemMain)>>>(tokens, ln2g, ln2b, dW2, db2, rW2, rb2,
                                            vb, ob, pg, pl, pb, out);
}

// round 9
// speedup vs baseline: 1.4524x; 1.1815x over previous
#include <cuda_runtime.h>
#include <cuda_bf16.h>
#include <mma.h>

using namespace nvcuda;
typedef __nv_bfloat16 bf16;

#define CC   128
#define NB   9
#define RPD  8
#define HID  128
#define NTOK 32768
#define TPB  32          // tokens per main block
#define MROW (TPB*NB)    // 288 edge rows
#define WS   272         // Wcat bf16 stride (cols 0-127 drive, 128-255 resist)

// ---- device scratch (no runtime allocation) ----
__device__ bf16  g_normbf[NTOK*CC];
__device__ float g_cd[NTOK*HID];
__device__ float g_cr[NTOK*HID];
__device__ bf16  g_Ad[CC*HID], g_Ar[CC*HID];   // Wn - Wd
__device__ bf16  g_Bd[CC*HID], g_Br[CC*HID];   // Wc + Wd
__device__ bf16  g_vWb[CC*CC], g_oWb[CC*CC];
__device__ float g_relbd[NB*HID], g_relbr[NB*HID];

__device__ __forceinline__ float gelu_exact(float x) {
    return 0.5f * x * (1.0f + erff(x * 0.70710678f));
}

// ================= kernel 0: fold weights, rel-bias tables =================
__global__ void k_prep(const float* __restrict__ dW1, const float* __restrict__ rW1,
                       const float* __restrict__ vW,  const float* __restrict__ oW,
                       const float* __restrict__ rel_pos,
                       const float* __restrict__ db1, const float* __restrict__ rb1)
{
    int i = blockIdx.x * blockDim.x + threadIdx.x;
    if (i >= CC*HID) return;
    int c = i >> 7, h = i & 127;
    g_Ad[i] = __float2bfloat16(dW1[(CC+c)*HID+h]   - dW1[(2*CC+c)*HID+h]);
    g_Bd[i] = __float2bfloat16(dW1[c*HID+h]        + dW1[(2*CC+c)*HID+h]);
    g_Ar[i] = __float2bfloat16(rW1[(CC+c)*HID+h]   - rW1[(2*CC+c)*HID+h]);
    g_Br[i] = __float2bfloat16(rW1[c*HID+h]        + rW1[(2*CC+c)*HID+h]);
    g_vWb[i] = __float2bfloat16(vW[i]);
    g_oWb[i] = __float2bfloat16(oW[i]);
    if (i < NB*HID) {
        int n = i >> 7;
        float sd = db1[h], sr = rb1[h];
        #pragma unroll
        for (int r = 0; r < RPD; r++) {
            float rp = rel_pos[n*RPD + r];
            sd += rp * dW1[(3*CC+r)*HID+h];
            sr += rp * rW1[(3*CC+r)*HID+h];
        }
        g_relbd[i] = sd; g_relbr[i] = sr;
    }
}

// ================= kernel 1: LayerNorm1 -> bf16 =================
__global__ void k_ln1(const float* __restrict__ tokens,
                      const float* __restrict__ g, const float* __restrict__ b)
{
    int wid = threadIdx.x >> 5, lane = threadIdx.x & 31;
    int row = blockIdx.x * 8 + wid;
    float4 v = reinterpret_cast<const float4*>(tokens + (size_t)row*CC)[lane];
    float s = v.x + v.y + v.z + v.w;
    #pragma unroll
    for (int o = 16; o; o >>= 1) s += __shfl_xor_sync(0xffffffffu, s, o);
    float mean = s * (1.0f/128.0f);
    float d0=v.x-mean, d1=v.y-mean, d2=v.z-mean, d3=v.w-mean;
    float q = d0*d0+d1*d1+d2*d2+d3*d3;
    #pragma unroll
    for (int o = 16; o; o >>= 1) q += __shfl_xor_sync(0xffffffffu, q, o);
    float rstd = rsqrtf(q * (1.0f/128.0f) + 1e-5f);
    float4 gg = reinterpret_cast<const float4*>(g)[lane];
    float4 bb = reinterpret_cast<const float4*>(b)[lane];
    __nv_bfloat162 p0 = __floats2bfloat162_rn(d0*rstd*gg.x+bb.x, d1*rstd*gg.y+bb.y);
    __nv_bfloat162 p1 = __floats2bfloat162_rn(d2*rstd*gg.z+bb.z, d3*rstd*gg.w+bb.w);
    uint2 pk; pk.x = *reinterpret_cast<unsigned int*>(&p0); pk.y = *reinterpret_cast<unsigned int*>(&p1);
    reinterpret_cast<uint2*>(g_normbf + (size_t)row*CC)[lane] = pk;
}

// ================= kernel 2: center GEMMs (split drive/resist by blockIdx.y) =========
#define CSMEM (2*128*136*2)
__global__ void __launch_bounds__(256) k_center()
{
    extern __shared__ char sm[];
    bf16* Xs = reinterpret_cast<bf16*>(sm);
    bf16* Ws = Xs + 128*136;
    int tid = threadIdx.x, wid = tid >> 5;
    int row0 = blockIdx.x * 128;
    int which = blockIdx.y;
    const bf16* Wg = which ? g_Br : g_Bd;
    float* outg = which ? g_cr : g_cd;
    for (int i = tid; i < 8192; i += 256) {
        int r = i >> 6, c = i & 63;
        reinterpret_cast<unsigned int*>(Ws)[r*68+c] = reinterpret_cast<const unsigned int*>(Wg)[i];
        reinterpret_cast<unsigned int*>(Xs)[r*68+c] =
            reinterpret_cast<const unsigned int*>(g_normbf + (size_t)row0*CC)[i];
    }
    __syncthreads();
    wmma::fragment<wmma::matrix_a,16,16,16,bf16,wmma::row_major> fa;
    wmma::fragment<wmma::matrix_b,16,16,16,bf16,wmma::row_major> fb;
    wmma::fragment<wmma::accumulator,16,16,16,float> acc[8];
    #pragma unroll
    for (int ct = 0; ct < 8; ct++) wmma::fill_fragment(acc[ct], 0.0f);
    for (int kt = 0; kt < 8; kt++) {
        wmma::load_matrix_sync(fa, Xs + wid*16*136 + kt*16, 136);
        #pragma unroll
        for (int ct = 0; ct < 8; ct++) {
            wmma::load_matrix_sync(fb, Ws + kt*16*136 + ct*16, 136);
            wmma::mma_sync(acc[ct], fa, fb, acc[ct]);
        }
    }
    #pragma unroll
    for (int ct = 0; ct < 8; ct++)
        wmma::store_matrix_sync(outg + (size_t)(row0+wid*16)*HID + ct*16, acc[ct], HID, wmma::mem_row_major);
}

// ================= main fused kernel =================
struct SmemMain {
    bf16 Wcat[128*WS];            // 69.6 KB
    bf16 Vs[MROW*136];            // 78.3 KB (later aliased by Ms/msg/Us)
    bf16 mv[TPB*136];             // 8.7 KB
    float Cds[TPB*132], Crs[TPB*132];   // 33.8 KB
    float relbd[NB*132], relbr[NB*132]; // 9.5 KB
    float w2d[128], w2r[128];
    float drive[MROW], resist[MROW], gate[MROW];
    float gsum[TPB], invm[TPB];
};

__global__ void __launch_bounds__(576, 1) k_main(
    const float* __restrict__ tokens,
    const float* __restrict__ ln2g, const float* __restrict__ ln2b,
    const float* __restrict__ dW2,  const float* __restrict__ db2,
    const float* __restrict__ rW2,  const float* __restrict__ rb2,
    const float* __restrict__ vb,   const float* __restrict__ ob,
    const float* __restrict__ pg, const float* __restrict__ pl, const float* __restrict__ pb,
    float* __restrict__ out)
{
    extern __shared__ char smraw[];
    SmemMain& S = *reinterpret_cast<SmemMain*>(smraw);
    const int tid = threadIdx.x, wid = tid >> 5, lane = tid & 31;
    const int bx = blockIdx.x;
    const int x0 = (bx & 3) << 5, y = (bx >> 2) & 127, b = bx >> 9;
    const int tokrow0 = (b*128 + y)*128 + x0;

    // ---- stage concatenated weight [Ad | Ar], biases, center terms ----
    for (int i = tid; i < 8192; i += 576) {
        int r = i >> 6, c = i & 63;
        unsigned int* Wu = reinterpret_cast<unsigned int*>(S.Wcat);
        Wu[r*(WS/2) + c]      = reinterpret_cast<const unsigned int*>(g_Ad)[i];
        Wu[r*(WS/2) + 64 + c] = reinterpret_cast<const unsigned int*>(g_Ar)[i];
    }
    for (int i = tid; i < NB*HID; i += 576) {
        int n = i >> 7, c = i & 127;
        S.relbd[n*132+c] = g_relbd[i]; S.relbr[n*132+c] = g_relbr[i];
    }
    for (int i = tid; i < TPB*128; i += 576) {
        int t = i >> 7, c = i & 127;
        S.Cds[t*132+c] = g_cd[(size_t)tokrow0*HID + i];
        S.Crs[t*132+c] = g_cr[(size_t)tokrow0*HID + i];
    }
    if (tid < 128) S.w2d[tid] = dW2[tid];
    else if (tid < 256) S.w2r[tid-128] = rW2[tid-128];

    // ---- gather scrambled neighborhood: Vs[t*9+n][c2] = norm[y+si-1, x+sj-1, c],
    //      where c*9+s = n*128+c2 (torch reshape semantics) ----
    for (int uidx = tid; uidx < TPB*144; uidx += 576) {
        int t = uidx / 144, rem = uidx - t*144;
        int s = rem >> 4, c0 = (rem & 15) << 3;
        int si = s / 3, sj = s - si*3;
        int yy = y + si - 1, xx = x0 + t + sj - 1;
        union { uint4 v; unsigned short h[8]; } pkt;
        if (yy >= 0 && yy < 128 && xx >= 0 && xx < 128) {
            pkt.v = *reinterpret_cast<const uint4*>(
                g_normbf + ((size_t)((b*128+yy)*128+xx))*CC + c0);
        } else {
            pkt.v = make_uint4(0,0,0,0);
        }
        unsigned short* vsrow = reinterpret_cast<unsigned short*>(S.Vs);
        #pragma unroll
        for (int k = 0; k < 8; k++) {
            int p = (c0 + k)*9 + s;
            vsrow[(t*9 + (p >> 7))*136 + (p & 127)] = pkt.h[k];
        }
    }
    __syncthreads();

    // ---- big GEMM: 18 warps = 18 bands; drive+resist interleaved, fa shared.
    //      Epilogue directly from accumulator fragments (sm_80 mapping). ----
    {
        const int band = wid;
        wmma::fragment<wmma::matrix_a,16,16,16,bf16,wmma::row_major> fa[8];
        #pragma unroll
        for (int kt = 0; kt < 8; kt++)
            wmma::load_matrix_sync(fa[kt], S.Vs + band*16*136 + kt*16, 136);

        const int g4 = lane >> 2, t4 = lane & 3;
        const int rowA = band*16 + g4, rowB = rowA + 8;
        const int tA = rowA/9, nA = rowA - tA*9;
        const int tB = rowB/9, nB = rowB - tB*9;
        const int c0l = t4*2;
        float pdA=0.f, pdB=0.f, prA=0.f, prB=0.f;

        wmma::fragment<wmma::matrix_b,16,16,16,bf16,wmma::row_major> fbd, fbr;
        wmma::fragment<wmma::accumulator,16,16,16,float> accd, accr;
        for (int ct = 0; ct < 8; ct++) {
            wmma::fill_fragment(accd, 0.0f);
            wmma::fill_fragment(accr, 0.0f);
            #pragma unroll
            for (int kt = 0; kt < 8; kt++) {
                wmma::load_matrix_sync(fbd, S.Wcat + kt*16*WS + ct*16, WS);
                wmma::load_matrix_sync(fbr, S.Wcat + kt*16*WS + 128 + ct*16, WS);
                wmma::mma_sync(accd, fa[kt], fbd, accd);
                wmma::mma_sync(accr, fa[kt], fbr, accr);
            }
            // fragment element mapping (sm_80+): e -> row (e&2 ? B : A),
            // col = ct*16 + 2*(lane&3) + (e&1) + ((e&4) ? 8 : 0)
            #pragma unroll
            for (int e = 0; e < 8; e++) {
                const int colc = ct*16 + c0l + (e & 1) + ((e & 4) << 1);
                const bool bh = (e & 2);
                const int tt = bh ? tB : tA, nn = bh ? nB : nA;
                float hd = accd.x[e] + S.Cds[tt*132+colc] + S.relbd[nn*132+colc];
                float hr = accr.x[e] + S.Crs[tt*132+colc] + S.relbr[nn*132+colc];
                float gd = gelu_exact(hd) * S.w2d[colc];
                float gr = gelu_exact(hr) * S.w2r[colc];
                if (bh) { pdB += gd; prB += gr; }
                else    { pdA += gd; prA += gr; }
            }
        }
        #pragma unroll
        for (int o = 1; o <= 2; o <<= 1) {
            pdA += __shfl_xor_sync(0xffffffffu, pdA, o);
            pdB += __shfl_xor_sync(0xffffffffu, pdB, o);
            prA += __shfl_xor_sync(0xffffffffu, prA, o);
            prB += __shfl_xor_sync(0xffffffffu, prB, o);
        }
        if (t4 == 0) {
            float db2v = db2[0], rb2v = rb2[0];
            S.drive[rowA]  = pdA + db2v;  S.drive[rowB]  = pdB + db2v;
            S.resist[rowA] = prA + rb2v;  S.resist[rowB] = prB + rb2v;
        }
    }
    __syncthreads();

    // ---- gate ----
    if (tid < MROW) {
        float gamma = pg[0], lam = pl[0], bias = pb[0];
        float rres = S.resist[tid];
        float sp = (rres > 20.f) ? rres : log1pf(expf(rres));
        float e = gamma * S.drive[tid] / (lam * sp + 1e-6f) + bias;
        e = fminf(fmaxf(e, -3.0f), 3.0f);
        S.gate[tid] = 1.0f / (1.0f + expf(-e));
    }
    __syncthreads();
    if (tid < TPB) {
        float sgm = 0.f;
        #pragma unroll
        for (int n2 = 0; n2 < 9; n2++) sgm += S.gate[tid*9+n2];
        S.gsum[tid] = sgm;
        S.invm[tid] = 1.0f / fmaxf(sgm, 1e-6f);
    }
    __syncthreads();
    // ---- gated neighbor sum -> mv (bf16 TPBx128) ----
    for (int uidx = tid; uidx < TPB*128; uidx += 576) {
        int t2 = uidx >> 7, c = uidx & 127;
        float sacc = 0.f;
        #pragma unroll
        for (int n2 = 0; n2 < 9; n2++)
            sacc += S.gate[t2*9+n2] * __bfloat162float(S.Vs[(t2*9+n2)*136 + c]);
        S.mv[t2*136 + c] = __float2bfloat16(sacc);
    }
    __syncthreads();   // Vs now dead; alias its space

    float* Ms  = reinterpret_cast<float*>(S.Vs);                   // TPBx128 f32
    bf16*  msg = reinterpret_cast<bf16*>(reinterpret_cast<char*>(S.Vs) + TPB*128*4);
    float* Us  = reinterpret_cast<float*>(reinterpret_cast<char*>(S.Vs) + TPB*128*4 + TPB*136*2);

    // ---- mv @ vW (16 warps: 2 row tiles x 8 col tiles) ----
    if (wid < 16) {
        int rt = wid >> 3, ctl = wid & 7;
        wmma::fragment<wmma::matrix_a,16,16,16,bf16,wmma::row_major> fa;
        wmma::fragment<wmma::matrix_b,16,16,16,bf16,wmma::row_major> fb;
        wmma::fragment<wmma::accumulator,16,16,16,float> acc;
        wmma::fill_fragment(acc, 0.0f);
        for (int kt = 0; kt < 8; kt++) {
            wmma::load_matrix_sync(fa, S.mv + rt*16*136 + kt*16, 136);
            wmma::load_matrix_sync(fb, g_vWb + kt*16*128 + ctl*16, 128);
            wmma::mma_sync(acc, fa, fb, acc);
        }
        wmma::store_matrix_sync(Ms + rt*16*128 + ctl*16, acc, 128, wmma::mem_row_major);
    }
    __syncthreads();
    for (int uidx = tid; uidx < TPB*128; uidx += 576) {
        int t2 = uidx >> 7, d = uidx & 127;
        float m = (Ms[uidx] + S.gsum[t2]*vb[d]) * S.invm[t2];
        msg[t2*136 + d] = __float2bfloat16(m);
    }
    __syncthreads();
    // ---- message @ oW ----
    if (wid < 16) {
        int rt = wid >> 3, ctl = wid & 7;
        wmma::fragment<wmma::matrix_a,16,16,16,bf16,wmma::row_major> fa;
        wmma::fragment<wmma::matrix_b,16,16,16,bf16,wmma::row_major> fb;
        wmma::fragment<wmma::accumulator,16,16,16,float> acc;
        wmma::fill_fragment(acc, 0.0f);
        for (int kt = 0; kt < 8; kt++) {
            wmma::load_matrix_sync(fa, msg + rt*16*136 + kt*16, 136);
            wmma::load_matrix_sync(fb, g_oWb + kt*16*128 + ctl*16, 128);
            wmma::mma_sync(acc, fa, fb, acc);
        }
        wmma::store_matrix_sync(Us + rt*16*128 + ctl*16, acc, 128, wmma::mem_row_major);
    }
    __syncthreads();
    // ---- LN2(tokens + update) ----
    for (int r = wid; r < TPB; r += 18) {
        size_t grow = (size_t)(tokrow0 + r) * CC;
        float4 tv = reinterpret_cast<const float4*>(tokens + grow)[lane];
        float4 uv = reinterpret_cast<const float4*>(Us + r*128)[lane];
        float4 ov = reinterpret_cast<const float4*>(ob)[lane];
        float v0 = tv.x+uv.x+ov.x, v1 = tv.y+uv.y+ov.y;
        float v2 = tv.z+uv.z+ov.z, v3 = tv.w+uv.w+ov.w;
        float s = v0+v1+v2+v3;
        #pragma unroll
        for (int o = 16; o; o >>= 1) s += __shfl_xor_sync(0xffffffffu, s, o);
        float mean = s * (1.0f/128.0f);
        float d0=v0-mean, d1=v1-mean, d2=v2-mean, d3=v3-mean;
        float q = d0*d0+d1*d1+d2*d2+d3*d3;
        #pragma unroll
        for (int o = 16; o; o >>= 1) q += __shfl_xor_sync(0xffffffffu, q, o);
        float rstd = rsqrtf(q * (1.0f/128.0f) + 1e-5f);
        float4 gg = reinterpret_cast<const float4*>(ln2g)[lane];
        float4 bb = reinterpret_cast<const float4*>(ln2b)[lane];
        float4 o4;
        o4.x = d0*rstd*gg.x+bb.x; o4.y = d1*rstd*gg.y+bb.y;
        o4.z = d2*rstd*gg.z+bb.z; o4.w = d3*rstd*gg.w+bb.w;
        reinterpret_cast<float4*>(out + grow)[lane] = o4;
    }
}

// ================= launch =================
extern "C" void kernel_launch(void* const* d_in, const int* in_sizes, int n_in,
                              void* d_out, int out_size)
{
    const float* tokens = (const float*)d_in[0];
    const float* ln1g   = (const float*)d_in[1];
    const float* ln1b   = (const float*)d_in[2];
    const float* ln2g   = (const float*)d_in[3];
    const float* ln2b   = (const float*)d_in[4];
    const float* relp   = (const float*)d_in[5];
    const float* dW1    = (const float*)d_in[6];
    const float* db1    = (const float*)d_in[7];
    const float* dW2    = (const float*)d_in[8];
    const float* db2    = (const float*)d_in[9];
    const float* rW1    = (const float*)d_in[10];
    const float* rb1    = (const float*)d_in[11];
    const float* rW2    = (const float*)d_in[12];
    const float* rb2    = (const float*)d_in[13];
    const float* vW     = (const float*)d_in[14];
    const float* vb     = (const float*)d_in[15];
    const float* oW     = (const float*)d_in[16];
    const float* ob     = (const float*)d_in[17];
    const float* pg     = (const float*)d_in[18];
    const float* pl     = (const float*)d_in[19];
    const float* pb     = (const float*)d_in[20];
    float* out = (float*)d_out;

    static_assert(sizeof(SmemMain) <= 227000, "smem too big");
    cudaFuncSetAttribute(k_center, cudaFuncAttributeMaxDynamicSharedMemorySize, CSMEM);
    cudaFuncSetAttribute(k_main, cudaFuncAttributeMaxDynamicSharedMemorySize, (int)sizeof(SmemMain));

    k_prep<<<64, 256>>>(dW1, rW1, vW, oW, relp, db1, rb1);
    k_ln1<<<4096, 256>>>(tokens, ln1g, ln1b);
    dim3 cgrid(256, 2);
    k_center<<<cgrid, 256, CSMEM>>>();
    k_main<<<1024, 576, sizeof(SmemMain)>>>(tokens, ln2g, ln2b, dW2, db2, rW2, rb2,
                                            vb, ob, pg, pl, pb, out);
}

// round 10
// speedup vs baseline: 1.6723x; 1.1514x over previous
#include <cuda_runtime.h>
#include <cuda_bf16.h>
#include <mma.h>

using namespace nvcuda;
typedef __nv_bfloat16 bf16;

#define CC   128
#define NB   9
#define RPD  8
#define HID  128
#define NTOK 32768
#define TPB  32          // tokens per main block
#define MROW (TPB*NB)    // 288 edge rows
#define WS   272         // Wcat bf16 stride (cols 0-127 drive, 128-255 resist)

// ---- device scratch (no runtime allocation) ----
__device__ bf16  g_normbf[NTOK*CC];
__device__ float g_cd[NTOK*HID];
__device__ float g_cr[NTOK*HID];
__device__ bf16  g_Ad[CC*HID], g_Ar[CC*HID];   // Wn - Wd
__device__ bf16  g_Bd[CC*HID], g_Br[CC*HID];   // Wc + Wd
__device__ bf16  g_vWb[CC*CC], g_oWb[CC*CC];
__device__ float g_relbd[NB*HID], g_relbr[NB*HID];

__device__ __forceinline__ float gelu_fast(float x) {
    float u = 0.7978845608f * x * (1.0f + 0.044715f * x * x);
    float t;
    asm("tanh.approx.f32 %0, %1;" : "=f"(t) : "f"(u));
    return 0.5f * x * (1.0f + t);
}

// ================= kernel 0: fold weights, rel-bias tables =================
__global__ void k_prep(const float* __restrict__ dW1, const float* __restrict__ rW1,
                       const float* __restrict__ vW,  const float* __restrict__ oW,
                       const float* __restrict__ rel_pos,
                       const float* __restrict__ db1, const float* __restrict__ rb1)
{
    int i = blockIdx.x * blockDim.x + threadIdx.x;
    if (i >= CC*HID) return;
    int c = i >> 7, h = i & 127;
    g_Ad[i] = __float2bfloat16(dW1[(CC+c)*HID+h]   - dW1[(2*CC+c)*HID+h]);
    g_Bd[i] = __float2bfloat16(dW1[c*HID+h]        + dW1[(2*CC+c)*HID+h]);
    g_Ar[i] = __float2bfloat16(rW1[(CC+c)*HID+h]   - rW1[(2*CC+c)*HID+h]);
    g_Br[i] = __float2bfloat16(rW1[c*HID+h]        + rW1[(2*CC+c)*HID+h]);
    g_vWb[i] = __float2bfloat16(vW[i]);
    g_oWb[i] = __float2bfloat16(oW[i]);
    if (i < NB*HID) {
        int n = i >> 7;
        float sd = db1[h], sr = rb1[h];
        #pragma unroll
        for (int r = 0; r < RPD; r++) {
            float rp = rel_pos[n*RPD + r];
            sd += rp * dW1[(3*CC+r)*HID+h];
            sr += rp * rW1[(3*CC+r)*HID+h];
        }
        g_relbd[i] = sd; g_relbr[i] = sr;
    }
}

// ================= kernel 1: LayerNorm1 -> bf16 =================
__global__ void k_ln1(const float* __restrict__ tokens,
                      const float* __restrict__ g, const float* __restrict__ b)
{
    int wid = threadIdx.x >> 5, lane = threadIdx.x & 31;
    int row = blockIdx.x * 8 + wid;
    float4 v = reinterpret_cast<const float4*>(tokens + (size_t)row*CC)[lane];
    float s = v.x + v.y + v.z + v.w;
    #pragma unroll
    for (int o = 16; o; o >>= 1) s += __shfl_xor_sync(0xffffffffu, s, o);
    float mean = s * (1.0f/128.0f);
    float d0=v.x-mean, d1=v.y-mean, d2=v.z-mean, d3=v.w-mean;
    float q = d0*d0+d1*d1+d2*d2+d3*d3;
    #pragma unroll
    for (int o = 16; o; o >>= 1) q += __shfl_xor_sync(0xffffffffu, q, o);
    float rstd = rsqrtf(q * (1.0f/128.0f) + 1e-5f);
    float4 gg = reinterpret_cast<const float4*>(g)[lane];
    float4 bb = reinterpret_cast<const float4*>(b)[lane];
    __nv_bfloat162 p0 = __floats2bfloat162_rn(d0*rstd*gg.x+bb.x, d1*rstd*gg.y+bb.y);
    __nv_bfloat162 p1 = __floats2bfloat162_rn(d2*rstd*gg.z+bb.z, d3*rstd*gg.w+bb.w);
    uint2 pk; pk.x = *reinterpret_cast<unsigned int*>(&p0); pk.y = *reinterpret_cast<unsigned int*>(&p1);
    reinterpret_cast<uint2*>(g_normbf + (size_t)row*CC)[lane] = pk;
}

// ================= kernel 2: center GEMMs (split drive/resist by blockIdx.y) =========
#define CSMEM (2*128*136*2)
__global__ void __launch_bounds__(256) k_center()
{
    extern __shared__ char sm[];
    bf16* Xs = reinterpret_cast<bf16*>(sm);
    bf16* Ws = Xs + 128*136;
    int tid = threadIdx.x, wid = tid >> 5;
    int row0 = blockIdx.x * 128;
    int which = blockIdx.y;
    const bf16* Wg = which ? g_Br : g_Bd;
    float* outg = which ? g_cr : g_cd;
    for (int i = tid; i < 8192; i += 256) {
        int r = i >> 6, c = i & 63;
        reinterpret_cast<unsigned int*>(Ws)[r*68+c] = reinterpret_cast<const unsigned int*>(Wg)[i];
        reinterpret_cast<unsigned int*>(Xs)[r*68+c] =
            reinterpret_cast<const unsigned int*>(g_normbf + (size_t)row0*CC)[i];
    }
    __syncthreads();
    wmma::fragment<wmma::matrix_a,16,16,16,bf16,wmma::row_major> fa;
    wmma::fragment<wmma::matrix_b,16,16,16,bf16,wmma::row_major> fb;
    wmma::fragment<wmma::accumulator,16,16,16,float> acc[8];
    #pragma unroll
    for (int ct = 0; ct < 8; ct++) wmma::fill_fragment(acc[ct], 0.0f);
    for (int kt = 0; kt < 8; kt++) {
        wmma::load_matrix_sync(fa, Xs + wid*16*136 + kt*16, 136);
        #pragma unroll
        for (int ct = 0; ct < 8; ct++) {
            wmma::load_matrix_sync(fb, Ws + kt*16*136 + ct*16, 136);
            wmma::mma_sync(acc[ct], fa, fb, acc[ct]);
        }
    }
    #pragma unroll
    for (int ct = 0; ct < 8; ct++)
        wmma::store_matrix_sync(outg + (size_t)(row0+wid*16)*HID + ct*16, acc[ct], HID, wmma::mem_row_major);
}

// ================= main fused kernel =================
struct SmemMain {
    bf16 Wcat[128*WS];            // 69.6 KB
    bf16 Vs[MROW*136];            // 78.3 KB (later aliased by Ms/msg/Us)
    bf16 mv[TPB*136];             // 8.7 KB
    float Cds[TPB*132], Crs[TPB*132];   // 33.8 KB
    float relbd[NB*132], relbr[NB*132]; // 9.5 KB
    float w2d[128], w2r[128];
    float drive[MROW], resist[MROW], gate[MROW];
    float gsum[TPB], invm[TPB];
};

__global__ void __launch_bounds__(576, 1) k_main(
    const float* __restrict__ tokens,
    const float* __restrict__ ln2g, const float* __restrict__ ln2b,
    const float* __restrict__ dW2,  const float* __restrict__ db2,
    const float* __restrict__ rW2,  const float* __restrict__ rb2,
    const float* __restrict__ vb,   const float* __restrict__ ob,
    const float* __restrict__ pg, const float* __restrict__ pl, const float* __restrict__ pb,
    float* __restrict__ out)
{
    extern __shared__ char smraw[];
    SmemMain& S = *reinterpret_cast<SmemMain*>(smraw);
    const int tid = threadIdx.x, wid = tid >> 5, lane = tid & 31;
    const int bx = blockIdx.x;
    const int x0 = (bx & 3) << 5, y = (bx >> 2) & 127, b = bx >> 9;
    const int tokrow0 = (b*128 + y)*128 + x0;

    // ---- stage concatenated weight [Ad | Ar], biases, center terms ----
    for (int i = tid; i < 8192; i += 576) {
        int r = i >> 6, c = i & 63;
        unsigned int* Wu = reinterpret_cast<unsigned int*>(S.Wcat);
        Wu[r*(WS/2) + c]      = reinterpret_cast<const unsigned int*>(g_Ad)[i];
        Wu[r*(WS/2) + 64 + c] = reinterpret_cast<const unsigned int*>(g_Ar)[i];
    }
    for (int i = tid; i < NB*HID; i += 576) {
        int n = i >> 7, c = i & 127;
        S.relbd[n*132+c] = g_relbd[i]; S.relbr[n*132+c] = g_relbr[i];
    }
    for (int i = tid; i < TPB*128; i += 576) {
        int t = i >> 7, c = i & 127;
        S.Cds[t*132+c] = g_cd[(size_t)tokrow0*HID + i];
        S.Crs[t*132+c] = g_cr[(size_t)tokrow0*HID + i];
    }
    if (tid < 128) S.w2d[tid] = dW2[tid];
    else if (tid < 256) S.w2r[tid-128] = rW2[tid-128];

    // ---- gather scrambled neighborhood: Vs[t*9+n][c2] = norm[y+si-1, x+sj-1, c],
    //      where c*9+s = n*128+c2 (torch reshape semantics) ----
    for (int uidx = tid; uidx < TPB*144; uidx += 576) {
        int t = uidx / 144, rem = uidx - t*144;
        int s = rem >> 4, c0 = (rem & 15) << 3;
        int si = s / 3, sj = s - si*3;
        int yy = y + si - 1, xx = x0 + t + sj - 1;
        union { uint4 v; unsigned short h[8]; } pkt;
        if (yy >= 0 && yy < 128 && xx >= 0 && xx < 128) {
            pkt.v = *reinterpret_cast<const uint4*>(
                g_normbf + ((size_t)((b*128+yy)*128+xx))*CC + c0);
        } else {
            pkt.v = make_uint4(0,0,0,0);
        }
        unsigned short* vsrow = reinterpret_cast<unsigned short*>(S.Vs);
        #pragma unroll
        for (int k = 0; k < 8; k++) {
            int p = (c0 + k)*9 + s;
            vsrow[(t*9 + (p >> 7))*136 + (p & 127)] = pkt.h[k];
        }
    }
    __syncthreads();

    // ---- big GEMM: warp = (row-pair rp 0..8, half d/r). 32 rows x 128 cols per warp.
    //      fa preloaded (16 frags), fb loaded once and shared across both bands.
    //      Epilogue directly from accumulator fragments (sm_80 mapping), float2 loads. ----
    {
        const int rp = wid >> 1, half = wid & 1;
        const int row0w = rp * 32;

        wmma::fragment<wmma::matrix_a,16,16,16,bf16,wmma::row_major> fa[2][8];
        #pragma unroll
        for (int bd = 0; bd < 2; bd++)
            #pragma unroll
            for (int kt = 0; kt < 8; kt++)
                wmma::load_matrix_sync(fa[bd][kt], S.Vs + (row0w + bd*16)*136 + kt*16, 136);

        const int g4 = lane >> 2, t4 = lane & 3;
        const int c0l = t4*2;
        // 4 output rows for this lane: bd*16 + g4 + {0,8}
        int rw[4], tw[4], nw[4];
        #pragma unroll
        for (int i = 0; i < 4; i++) {
            rw[i] = row0w + (i>>1)*16 + (i&1)*8 + g4;   // i = bd*2 + hi
            tw[i] = rw[i] / 9; nw[i] = rw[i] - tw[i]*9;
        }
        const float* Cs = half ? S.Crs : S.Cds;
        const float* Rb = half ? S.relbr : S.relbd;
        const float* w2 = half ? S.w2r : S.w2d;
        float psum[4] = {0.f, 0.f, 0.f, 0.f};

        wmma::fragment<wmma::matrix_b,16,16,16,bf16,wmma::row_major> fb;
        wmma::fragment<wmma::accumulator,16,16,16,float> accA, accB;
        for (int ct = 0; ct < 8; ct++) {
            wmma::fill_fragment(accA, 0.0f);
            wmma::fill_fragment(accB, 0.0f);
            #pragma unroll
            for (int kt = 0; kt < 8; kt++) {
                wmma::load_matrix_sync(fb, S.Wcat + kt*16*WS + half*128 + ct*16, WS);
                wmma::mma_sync(accA, fa[0][kt], fb, accA);
                wmma::mma_sync(accB, fa[1][kt], fb, accB);
            }
            // element e: row = g4 + (e&2 ? 8:0); col = ct*16 + 2*(lane&3) + (e&1) + (e&4 ? 8:0)
            #pragma unroll
            for (int bd = 0; bd < 2; bd++) {
                const float* ax = bd ? accB.x : accA.x;
                #pragma unroll
                for (int ee = 0; ee < 8; ee += 2) {
                    const int colc = ct*16 + c0l + ((ee & 4) << 1);
                    const int idx = bd*2 + ((ee & 2) >> 1);
                    float2 cv = *reinterpret_cast<const float2*>(&Cs[tw[idx]*132 + colc]);
                    float2 rv = *reinterpret_cast<const float2*>(&Rb[nw[idx]*132 + colc]);
                    float2 wv = *reinterpret_cast<const float2*>(&w2[colc]);
                    float h0 = ax[ee]   + cv.x + rv.x;
                    float h1 = ax[ee+1] + cv.y + rv.y;
                    psum[idx] += gelu_fast(h0)*wv.x + gelu_fast(h1)*wv.y;
                }
            }
        }
        #pragma unroll
        for (int i = 0; i < 4; i++) {
            #pragma unroll
            for (int o = 1; o <= 2; o <<= 1)
                psum[i] += __shfl_xor_sync(0xffffffffu, psum[i], o);
        }
        if (t4 == 0) {
            float b2v = half ? rb2[0] : db2[0];
            float* dst = half ? S.resist : S.drive;
            #pragma unroll
            for (int i = 0; i < 4; i++) dst[rw[i]] = psum[i] + b2v;
        }
    }
    __syncthreads();

    // ---- gate ----
    if (tid < MROW) {
        float gamma = pg[0], lam = pl[0], bias = pb[0];
        float rres = S.resist[tid];
        float sp = (rres > 20.f) ? rres : log1pf(expf(rres));
        float e = gamma * S.drive[tid] / (lam * sp + 1e-6f) + bias;
        e = fminf(fmaxf(e, -3.0f), 3.0f);
        S.gate[tid] = 1.0f / (1.0f + expf(-e));
    }
    __syncthreads();
    if (tid < TPB) {
        float sgm = 0.f;
        #pragma unroll
        for (int n2 = 0; n2 < 9; n2++) sgm += S.gate[tid*9+n2];
        S.gsum[tid] = sgm;
        S.invm[tid] = 1.0f / fmaxf(sgm, 1e-6f);
    }
    __syncthreads();
    // ---- gated neighbor sum -> mv (bf16 TPBx128), bf16x2 vectorized ----
    for (int uidx = tid; uidx < TPB*64; uidx += 576) {
        int t2 = uidx >> 6, cpair = (uidx & 63) << 1;
        float sx = 0.f, sy = 0.f;
        #pragma unroll
        for (int n2 = 0; n2 < 9; n2++) {
            float gt = S.gate[t2*9+n2];
            __nv_bfloat162 vv = *reinterpret_cast<const __nv_bfloat162*>(
                &S.Vs[(t2*9+n2)*136 + cpair]);
            float2 vf = __bfloat1622float2(vv);
            sx += gt*vf.x; sy += gt*vf.y;
        }
        *reinterpret_cast<__nv_bfloat162*>(&S.mv[t2*136 + cpair]) =
            __floats2bfloat162_rn(sx, sy);
    }
    __syncthreads();   // Vs now dead; alias its space

    float* Ms  = reinterpret_cast<float*>(S.Vs);                   // TPBx128 f32
    bf16*  msg = reinterpret_cast<bf16*>(reinterpret_cast<char*>(S.Vs) + TPB*128*4);
    float* Us  = reinterpret_cast<float*>(reinterpret_cast<char*>(S.Vs) + TPB*128*4 + TPB*136*2);

    // ---- mv @ vW (16 warps: 2 row tiles x 8 col tiles) ----
    if (wid < 16) {
        int rt = wid >> 3, ctl = wid & 7;
        wmma::fragment<wmma::matrix_a,16,16,16,bf16,wmma::row_major> fa;
        wmma::fragment<wmma::matrix_b,16,16,16,bf16,wmma::row_major> fb;
        wmma::fragment<wmma::accumulator,16,16,16,float> acc;
        wmma::fill_fragment(acc, 0.0f);
        for (int kt = 0; kt < 8; kt++) {
            wmma::load_matrix_sync(fa, S.mv + rt*16*136 + kt*16, 136);
            wmma::load_matrix_sync(fb, g_vWb + kt*16*128 + ctl*16, 128);
            wmma::mma_sync(acc, fa, fb, acc);
        }
        wmma::store_matrix_sync(Ms + rt*16*128 + ctl*16, acc, 128, wmma::mem_row_major);
    }
    __syncthreads();
    for (int uidx = tid; uidx < TPB*128; uidx += 576) {
        int t2 = uidx >> 7, d = uidx & 127;
        float m = (Ms[uidx] + S.gsum[t2]*vb[d]) * S.invm[t2];
        msg[t2*136 + d] = __float2bfloat16(m);
    }
    __syncthreads();
    // ---- message @ oW ----
    if (wid < 16) {
        int rt = wid >> 3, ctl = wid & 7;
        wmma::fragment<wmma::matrix_a,16,16,16,bf16,wmma::row_major> fa;
        wmma::fragment<wmma::matrix_b,16,16,16,bf16,wmma::row_major> fb;
        wmma::fragment<wmma::accumulator,16,16,16,float> acc;
        wmma::fill_fragment(acc, 0.0f);
        for (int kt = 0; kt < 8; kt++) {
            wmma::load_matrix_sync(fa, msg + rt*16*136 + kt*16, 136);
            wmma::load_matrix_sync(fb, g_oWb + kt*16*128 + ctl*16, 128);
            wmma::mma_sync(acc, fa, fb, acc);
        }
        wmma::store_matrix_sync(Us + rt*16*128 + ctl*16, acc, 128, wmma::mem_row_major);
    }
    __syncthreads();
    // ---- LN2(tokens + update) ----
    for (int r = wid; r < TPB; r += 18) {
        size_t grow = (size_t)(tokrow0 + r) * CC;
        float4 tv = reinterpret_cast<const float4*>(tokens + grow)[lane];
        float4 uv = reinterpret_cast<const float4*>(Us + r*128)[lane];
        float4 ov = reinterpret_cast<const float4*>(ob)[lane];
        float v0 = tv.x+uv.x+ov.x, v1 = tv.y+uv.y+ov.y;
        float v2 = tv.z+uv.z+ov.z, v3 = tv.w+uv.w+ov.w;
        float s = v0+v1+v2+v3;
        #pragma unroll
        for (int o = 16; o; o >>= 1) s += __shfl_xor_sync(0xffffffffu, s, o);
        float mean = s * (1.0f/128.0f);
        float d0=v0-mean, d1=v1-mean, d2=v2-mean, d3=v3-mean;
        float q = d0*d0+d1*d1+d2*d2+d3*d3;
        #pragma unroll
        for (int o = 16; o; o >>= 1) q += __shfl_xor_sync(0xffffffffu, q, o);
        float rstd = rsqrtf(q * (1.0f/128.0f) + 1e-5f);
        float4 gg = reinterpret_cast<const float4*>(ln2g)[lane];
        float4 bb = reinterpret_cast<const float4*>(ln2b)[lane];
        float4 o4;
        o4.x = d0*rstd*gg.x+bb.x; o4.y = d1*rstd*gg.y+bb.y;
        o4.z = d2*rstd*gg.z+bb.z; o4.w = d3*rstd*gg.w+bb.w;
        reinterpret_cast<float4*>(out + grow)[lane] = o4;
    }
}

// ================= launch =================
extern "C" void kernel_launch(void* const* d_in, const int* in_sizes, int n_in,
                              void* d_out, int out_size)
{
    const float* tokens = (const float*)d_in[0];
    const float* ln1g   = (const float*)d_in[1];
    const float* ln1b   = (const float*)d_in[2];
    const float* ln2g   = (const float*)d_in[3];
    const float* ln2b   = (const float*)d_in[4];
    const float* relp   = (const float*)d_in[5];
    const float* dW1    = (const float*)d_in[6];
    const float* db1    = (const float*)d_in[7];
    const float* dW2    = (const float*)d_in[8];
    const float* db2    = (const float*)d_in[9];
    const float* rW1    = (const float*)d_in[10];
    const float* rb1    = (const float*)d_in[11];
    const float* rW2    = (const float*)d_in[12];
    const float* rb2    = (const float*)d_in[13];
    const float* vW     = (const float*)d_in[14];
    const float* vb     = (const float*)d_in[15];
    const float* oW     = (const float*)d_in[16];
    const float* ob     = (const float*)d_in[17];
    const float* pg     = (const float*)d_in[18];
    const float* pl     = (const float*)d_in[19];
    const float* pb     = (const float*)d_in[20];
    float* out = (float*)d_out;

    static_assert(sizeof(SmemMain) <= 227000, "smem too big");
    cudaFuncSetAttribute(k_center, cudaFuncAttributeMaxDynamicSharedMemorySize, CSMEM);
    cudaFuncSetAttribute(k_main, cudaFuncAttributeMaxDynamicSharedMemorySize, (int)sizeof(SmemMain));

    k_prep<<<64, 256>>>(dW1, rW1, vW, oW, relp, db1, rb1);
    k_ln1<<<4096, 256>>>(tokens, ln1g, ln1b);
    dim3 cgrid(256, 2);
    k_center<<<cgrid, 256, CSMEM>>>();
    k_main<<<1024, 576, sizeof(SmemMain)>>>(tokens, ln2g, ln2b, dW2, db2, rW2, rb2,
                                            vb, ob, pg, pl, pb, out);
}